// round 1
// baseline (speedup 1.0000x reference)
#include <cuda_runtime.h>
#include <cub/cub.cuh>
#include <cstdint>
#include <math.h>

// Problem shape (fixed): B=4, H=8, S=1024, D=64
#define SLEN 1024
#define HD   64
#define NBH  32
#define NROWS (NBH * SLEN)          // 32768
#define NTOT  ((size_t)NROWS * SLEN) // 33554432 = 2^25

// ---------------- scratch (static device globals; no allocations) ----------
__device__ float g_score[NROWS * SLEN];                 // 128 MiB
__device__ unsigned long long g_keyA[NROWS * SLEN];     // 256 MiB
__device__ unsigned long long g_keyB[NROWS * SLEN];     // 256 MiB
__device__ float g_invq[NROWS];
__device__ float g_invk[NROWS];
__device__ float g_invsum[NROWS];
__device__ unsigned char g_temp[96u * 1024u * 1024u];   // CUB temp storage

// ---------------- f32x2 packed-FMA helpers (sm_103a) -----------------------
__device__ __forceinline__ unsigned long long pack2(float a, float b) {
    unsigned long long r;
    asm("mov.b64 %0, {%1,%2};" : "=l"(r) : "f"(a), "f"(b));
    return r;
}
__device__ __forceinline__ unsigned long long fma2(unsigned long long a,
                                                   unsigned long long b,
                                                   unsigned long long c) {
    unsigned long long d;
    asm("fma.rn.f32x2 %0, %1, %2, %3;" : "=l"(d) : "l"(a), "l"(b), "l"(c));
    return d;
}
__device__ __forceinline__ float2 unpack2(unsigned long long v) {
    float2 f;
    asm("mov.b64 {%0,%1}, %2;" : "=f"(f.x), "=f"(f.y) : "l"(v));
    return f;
}

__device__ __forceinline__ unsigned long long make_key(float v, unsigned idx) {
    unsigned bits = __float_as_uint(v);
    unsigned lo = idx | (bits & 0x80000000u) | ((v == 0.0f) ? 0x40000000u : 0u);
    return ((unsigned long long)(bits & 0x7fffffffu) << 32) | lo;
}

// ---------------- kernel 1: inverse row norms ------------------------------
__global__ __launch_bounds__(256) void norms_kernel(const float* __restrict__ Q,
                                                    const float* __restrict__ K) {
    int w = (blockIdx.x * 256 + threadIdx.x) >> 5;   // global warp id: 0..65535
    int lane = threadIdx.x & 31;
    const float* src;
    float* dst;
    int row;
    if (w < NROWS) { src = Q; dst = g_invq; row = w; }
    else           { src = K; dst = g_invk; row = w - NROWS; }
    const float* p = src + (size_t)row * HD;
    float a = p[lane], b = p[lane + 32];
    float s = a * a + b * b;
    #pragma unroll
    for (int o = 16; o; o >>= 1) s += __shfl_xor_sync(0xffffffffu, s, o);
    if (lane == 0) dst[row] = 1.0f / (sqrtf(s) + 1e-5f);
}

// ---------------- kernel 2: score GEMM + key emission ----------------------
// Per block: 64x64 tile of score[bh], fp32 via packed f32x2.
__global__ __launch_bounds__(256) void score_kernel(const float* __restrict__ Q,
                                                    const float* __restrict__ K) {
    __shared__ __align__(16) float Qs[64][68];   // [k][i]
    __shared__ __align__(16) float Ks[64][68];   // [k][j]
    int bh = blockIdx.z;
    int i0 = blockIdx.y * 64, j0 = blockIdx.x * 64;
    const float* Qb = Q + (size_t)bh * SLEN * HD;
    const float* Kb = K + (size_t)bh * SLEN * HD;
    int tx = threadIdx.x, ty = threadIdx.y;
    int tid = ty * 16 + tx;

    #pragma unroll
    for (int t = 0; t < 16; t++) {
        int idx = tid + t * 256;
        int r = idx >> 6, k = idx & 63;
        Qs[k][r] = Qb[(i0 + r) * HD + k];
        Ks[k][r] = Kb[(j0 + r) * HD + k];
    }
    __syncthreads();

    unsigned long long acc[4][2];
    #pragma unroll
    for (int m = 0; m < 4; m++) { acc[m][0] = 0ull; acc[m][1] = 0ull; }

    #pragma unroll
    for (int k = 0; k < 64; k++) {
        float4 av = *(const float4*)&Qs[k][ty * 4];
        ulonglong2 bv = *(const ulonglong2*)&Ks[k][tx * 4];
        unsigned long long a;
        a = pack2(av.x, av.x);
        acc[0][0] = fma2(a, bv.x, acc[0][0]); acc[0][1] = fma2(a, bv.y, acc[0][1]);
        a = pack2(av.y, av.y);
        acc[1][0] = fma2(a, bv.x, acc[1][0]); acc[1][1] = fma2(a, bv.y, acc[1][1]);
        a = pack2(av.z, av.z);
        acc[2][0] = fma2(a, bv.x, acc[2][0]); acc[2][1] = fma2(a, bv.y, acc[2][1]);
        a = pack2(av.w, av.w);
        acc[3][0] = fma2(a, bv.x, acc[3][0]); acc[3][1] = fma2(a, bv.y, acc[3][1]);
    }

    int jb = j0 + tx * 4;
    int rowk = bh * SLEN + jb;
    float ik0 = g_invk[rowk], ik1 = g_invk[rowk + 1];
    float ik2 = g_invk[rowk + 2], ik3 = g_invk[rowk + 3];

    #pragma unroll
    for (int m = 0; m < 4; m++) {
        int i = i0 + ty * 4 + m;
        int row = bh * SLEN + i;
        float iq = g_invq[row];
        float2 c01 = unpack2(acc[m][0]);
        float2 c23 = unpack2(acc[m][1]);
        float v0 = c01.x * iq * ik0;
        float v1 = c01.y * iq * ik1;
        float v2 = c23.x * iq * ik2;
        float v3 = c23.y * iq * ik3;
        unsigned idx = ((unsigned)row << 10) + (unsigned)jb;
        *(float4*)&g_score[idx] = make_float4(v0, v1, v2, v3);
        ulonglong2 ka, kb;
        ka.x = make_key(v0, idx);     ka.y = make_key(v1, idx + 1);
        kb.x = make_key(v2, idx + 2); kb.y = make_key(v3, idx + 3);
        *(ulonglong2*)&g_keyA[idx] = ka;
        *(ulonglong2*)&g_keyA[idx + 2] = kb;
    }
}

// ---------------- kernel 3: rank transform scatter -------------------------
__global__ __launch_bounds__(256) void transform_kernel(
        const unsigned long long* __restrict__ sorted) {
    unsigned p = blockIdx.x * 256 + threadIdx.x;
    unsigned long long kv = sorted[p];
    unsigned lo = (unsigned)kv;
    unsigned idx = lo & 0x01FFFFFFu;
    // ranked = p/(n-1) + 1/n  (computed in double, matches f32 reference to ~1e-7)
    double r = (double)p * (1.0 / 33554431.0) + (1.0 / 33554432.0);
    float t = -logf((float)r);
    if (lo & 0x40000000u) t = 0.0f;    // sign(score)==0 case
    if (lo & 0x80000000u) t = -t;      // apply original sign
    g_score[idx] = t;
}

// ---------------- kernel 4: row L1 sums ------------------------------------
__global__ __launch_bounds__(256) void rowsum_kernel() {
    int w = (blockIdx.x * 256 + threadIdx.x) >> 5;   // 0..32767
    int lane = threadIdx.x & 31;
    const float* p = g_score + (size_t)w * SLEN;
    float s = 0.0f;
    #pragma unroll
    for (int m = 0; m < 32; m++) s += fabsf(p[lane + m * 32]);
    #pragma unroll
    for (int o = 16; o; o >>= 1) s += __shfl_xor_sync(0xffffffffu, s, o);
    if (lane == 0) g_invsum[w] = 1.0f / s;
}

// ---------------- kernel 5: output GEMM O = (P * invsum) @ V ---------------
__global__ __launch_bounds__(256) void out_kernel(const float* __restrict__ V,
                                                  float* __restrict__ O) {
    __shared__ __align__(16) float Ps[64][68];   // [k][r] (transposed P chunk)
    __shared__ __align__(16) float Vs[64][68];   // [k][d]
    int bh = blockIdx.z;
    int i0 = blockIdx.y * 64;
    const float* Pb = g_score + (size_t)bh * SLEN * SLEN;
    const float* Vb = V + (size_t)bh * SLEN * HD;
    int tx = threadIdx.x, ty = threadIdx.y;
    int tid = ty * 16 + tx;

    unsigned long long acc[4][2];
    #pragma unroll
    for (int m = 0; m < 4; m++) { acc[m][0] = 0ull; acc[m][1] = 0ull; }

    for (int k0 = 0; k0 < SLEN; k0 += 64) {
        #pragma unroll
        for (int t = 0; t < 16; t++) {
            int idx = tid + t * 256;
            int r = idx >> 6, k = idx & 63;
            Ps[k][r] = Pb[(size_t)(i0 + r) * SLEN + (k0 + k)];
            Vs[r][k] = Vb[(k0 + r) * HD + k];   // r=kv-row, k=d  (coalesced)
        }
        __syncthreads();
        #pragma unroll
        for (int k = 0; k < 64; k++) {
            float4 av = *(const float4*)&Ps[k][ty * 4];
            ulonglong2 bv = *(const ulonglong2*)&Vs[k][tx * 4];
            unsigned long long a;
            a = pack2(av.x, av.x);
            acc[0][0] = fma2(a, bv.x, acc[0][0]); acc[0][1] = fma2(a, bv.y, acc[0][1]);
            a = pack2(av.y, av.y);
            acc[1][0] = fma2(a, bv.x, acc[1][0]); acc[1][1] = fma2(a, bv.y, acc[1][1]);
            a = pack2(av.z, av.z);
            acc[2][0] = fma2(a, bv.x, acc[2][0]); acc[2][1] = fma2(a, bv.y, acc[2][1]);
            a = pack2(av.w, av.w);
            acc[3][0] = fma2(a, bv.x, acc[3][0]); acc[3][1] = fma2(a, bv.y, acc[3][1]);
        }
        __syncthreads();
    }

    int d0 = tx * 4;
    #pragma unroll
    for (int m = 0; m < 4; m++) {
        int row = bh * SLEN + i0 + ty * 4 + m;
        float s = g_invsum[row];
        float2 c01 = unpack2(acc[m][0]);
        float2 c23 = unpack2(acc[m][1]);
        *(float4*)&O[(size_t)row * HD + d0] =
            make_float4(c01.x * s, c01.y * s, c23.x * s, c23.y * s);
    }
}

// ---------------- launcher --------------------------------------------------
extern "C" void kernel_launch(void* const* d_in, const int* in_sizes, int n_in,
                              void* d_out, int out_size) {
    const float* Q = (const float*)d_in[0];
    const float* K = (const float*)d_in[1];
    const float* V = (const float*)d_in[2];
    float* O = (float*)d_out;

    norms_kernel<<<8192, 256>>>(Q, K);

    dim3 blk(16, 16);
    score_kernel<<<dim3(16, 16, NBH), blk>>>(Q, K);

    void *tmp, *ka, *kb;
    cudaGetSymbolAddress(&tmp, g_temp);
    cudaGetSymbolAddress(&ka, g_keyA);
    cudaGetSymbolAddress(&kb, g_keyB);
    cub::DoubleBuffer<unsigned long long> db((unsigned long long*)ka,
                                             (unsigned long long*)kb);
    size_t temp_bytes = sizeof(g_temp);
    // Stable LSD radix sort on bits [32,64) only (abs-value key); ties keep
    // original (index) order == jnp stable argsort semantics.
    cub::DeviceRadixSort::SortKeys(tmp, temp_bytes, db, (int)NTOT, 32, 64);

    transform_kernel<<<(unsigned)(NTOT / 256), 256>>>(db.Current());
    rowsum_kernel<<<NROWS / 8, 256>>>();
    out_kernel<<<dim3(1, 16, NBH), blk>>>(V, O);
}

// round 2
// speedup vs baseline: 3.2093x; 3.2093x over previous
#include <cuda_runtime.h>
#include <cub/cub.cuh>
#include <cstdint>
#include <math.h>

// Problem shape (fixed): B=4, H=8, S=1024, D=64
#define SLEN 1024
#define HD   64
#define NBH  32
#define NROWS (NBH * SLEN)           // 32768
#define NTOT  ((size_t)NROWS * SLEN) // 33554432 = 2^25
#define NBINS 16777216               // 2^24 histogram bins (top-24 abs-float bits)

// ---------------- scratch (static device globals; no allocations) ----------
__device__ float g_score[NROWS * SLEN];          // 128 MiB
__device__ unsigned int g_hist[NBINS];           // 64 MiB
__device__ float g_invq[NROWS];
__device__ float g_invk[NROWS];
__device__ float g_invsum[NROWS];
__device__ unsigned char g_temp[16u * 1024u * 1024u];  // CUB scan temp

// ---------------- f32x2 packed-FMA helpers (sm_103a) -----------------------
__device__ __forceinline__ unsigned long long pack2(float a, float b) {
    unsigned long long r;
    asm("mov.b64 %0, {%1,%2};" : "=l"(r) : "f"(a), "f"(b));
    return r;
}
__device__ __forceinline__ unsigned long long fma2(unsigned long long a,
                                                   unsigned long long b,
                                                   unsigned long long c) {
    unsigned long long d;
    asm("fma.rn.f32x2 %0, %1, %2, %3;" : "=l"(d) : "l"(a), "l"(b), "l"(c));
    return d;
}
__device__ __forceinline__ float2 unpack2(unsigned long long v) {
    float2 f;
    asm("mov.b64 {%0,%1}, %2;" : "=f"(f.x), "=f"(f.y) : "l"(v));
    return f;
}

__device__ __forceinline__ unsigned bin_of(float v) {
    unsigned b = __float_as_uint(fabsf(v)) >> 7;   // monotone in |v|
    return min(b, (unsigned)(NBINS - 1));
}

// ---------------- kernel 0: zero histogram ---------------------------------
__global__ __launch_bounds__(256) void zero_hist_kernel() {
    unsigned i = blockIdx.x * 256 + threadIdx.x;
    ((uint4*)g_hist)[i] = make_uint4(0u, 0u, 0u, 0u);
}

// ---------------- kernel 1: inverse row norms ------------------------------
__global__ __launch_bounds__(256) void norms_kernel(const float* __restrict__ Q,
                                                    const float* __restrict__ K) {
    int w = (blockIdx.x * 256 + threadIdx.x) >> 5;   // global warp id: 0..65535
    int lane = threadIdx.x & 31;
    const float* src;
    float* dst;
    int row;
    if (w < NROWS) { src = Q; dst = g_invq; row = w; }
    else           { src = K; dst = g_invk; row = w - NROWS; }
    const float* p = src + (size_t)row * HD;
    float a = p[lane], b = p[lane + 32];
    float s = a * a + b * b;
    #pragma unroll
    for (int o = 16; o; o >>= 1) s += __shfl_xor_sync(0xffffffffu, s, o);
    if (lane == 0) dst[row] = 1.0f / (sqrtf(s) + 1e-5f);
}

// ---------------- kernel 2: score GEMM + fused histogram -------------------
// Per block: 64x64 tile of score[bh], fp32 via packed f32x2.
__global__ __launch_bounds__(256) void score_kernel(const float* __restrict__ Q,
                                                    const float* __restrict__ K) {
    __shared__ __align__(16) float Qs[64][68];   // [k][i]
    __shared__ __align__(16) float Ks[64][68];   // [k][j]
    int bh = blockIdx.z;
    int i0 = blockIdx.y * 64, j0 = blockIdx.x * 64;
    const float* Qb = Q + (size_t)bh * SLEN * HD;
    const float* Kb = K + (size_t)bh * SLEN * HD;
    int tx = threadIdx.x, ty = threadIdx.y;
    int tid = ty * 16 + tx;

    #pragma unroll
    for (int t = 0; t < 16; t++) {
        int idx = tid + t * 256;
        int r = idx >> 6, k = idx & 63;
        Qs[k][r] = Qb[(i0 + r) * HD + k];
        Ks[k][r] = Kb[(j0 + r) * HD + k];
    }
    __syncthreads();

    unsigned long long acc[4][2];
    #pragma unroll
    for (int m = 0; m < 4; m++) { acc[m][0] = 0ull; acc[m][1] = 0ull; }

    #pragma unroll
    for (int k = 0; k < 64; k++) {
        float4 av = *(const float4*)&Qs[k][ty * 4];
        ulonglong2 bv = *(const ulonglong2*)&Ks[k][tx * 4];
        unsigned long long a;
        a = pack2(av.x, av.x);
        acc[0][0] = fma2(a, bv.x, acc[0][0]); acc[0][1] = fma2(a, bv.y, acc[0][1]);
        a = pack2(av.y, av.y);
        acc[1][0] = fma2(a, bv.x, acc[1][0]); acc[1][1] = fma2(a, bv.y, acc[1][1]);
        a = pack2(av.z, av.z);
        acc[2][0] = fma2(a, bv.x, acc[2][0]); acc[2][1] = fma2(a, bv.y, acc[2][1]);
        a = pack2(av.w, av.w);
        acc[3][0] = fma2(a, bv.x, acc[3][0]); acc[3][1] = fma2(a, bv.y, acc[3][1]);
    }

    int jb = j0 + tx * 4;
    int rowk = bh * SLEN + jb;
    float ik0 = g_invk[rowk], ik1 = g_invk[rowk + 1];
    float ik2 = g_invk[rowk + 2], ik3 = g_invk[rowk + 3];

    #pragma unroll
    for (int m = 0; m < 4; m++) {
        int i = i0 + ty * 4 + m;
        int row = bh * SLEN + i;
        float iq = g_invq[row];
        float2 c01 = unpack2(acc[m][0]);
        float2 c23 = unpack2(acc[m][1]);
        float v0 = c01.x * iq * ik0;
        float v1 = c01.y * iq * ik1;
        float v2 = c23.x * iq * ik2;
        float v3 = c23.y * iq * ik3;
        unsigned idx = ((unsigned)row << 10) + (unsigned)jb;
        *(float4*)&g_score[idx] = make_float4(v0, v1, v2, v3);
        atomicAdd(&g_hist[bin_of(v0)], 1u);
        atomicAdd(&g_hist[bin_of(v1)], 1u);
        atomicAdd(&g_hist[bin_of(v2)], 1u);
        atomicAdd(&g_hist[bin_of(v3)], 1u);
    }
}

// ---------------- kernel 3: rank assignment + transform + row L1 sums ------
// One block per row (1024 threads). Each element's global rank = scanned
// prefix for its bin + atomic arrival order within the bin (distinct ranks).
__global__ __launch_bounds__(1024) void rank_kernel() {
    __shared__ float red[32];
    int row = blockIdx.x;
    int j = threadIdx.x;
    size_t idx = (size_t)row * SLEN + j;
    float v = g_score[idx];
    unsigned p = atomicAdd(&g_hist[bin_of(v)], 1u);
    double r = (double)p * (1.0 / 33554431.0) + (1.0 / 33554432.0);
    float t = -logf((float)r);
    float out = (v > 0.0f) ? t : ((v < 0.0f) ? -t : 0.0f);
    g_score[idx] = out;

    // block reduction of |out| for the row L1 norm
    float s = fabsf(out);
    #pragma unroll
    for (int o = 16; o; o >>= 1) s += __shfl_xor_sync(0xffffffffu, s, o);
    if ((j & 31) == 0) red[j >> 5] = s;
    __syncthreads();
    if (j < 32) {
        s = red[j];
        #pragma unroll
        for (int o = 16; o; o >>= 1) s += __shfl_xor_sync(0xffffffffu, s, o);
        if (j == 0) g_invsum[row] = 1.0f / s;
    }
}

// ---------------- kernel 4: output GEMM O = (P * invsum) @ V ---------------
__global__ __launch_bounds__(256) void out_kernel(const float* __restrict__ V,
                                                  float* __restrict__ O) {
    __shared__ __align__(16) float Ps[64][68];   // [k][r]
    __shared__ __align__(16) float Vs[64][68];   // [k][d]
    int bh = blockIdx.z;
    int i0 = blockIdx.y * 64;
    const float* Pb = g_score + (size_t)bh * SLEN * SLEN;
    const float* Vb = V + (size_t)bh * SLEN * HD;
    int tx = threadIdx.x, ty = threadIdx.y;
    int tid = ty * 16 + tx;

    unsigned long long acc[4][2];
    #pragma unroll
    for (int m = 0; m < 4; m++) { acc[m][0] = 0ull; acc[m][1] = 0ull; }

    for (int k0 = 0; k0 < SLEN; k0 += 64) {
        #pragma unroll
        for (int t = 0; t < 16; t++) {
            int idx = tid + t * 256;
            int r = idx >> 6, k = idx & 63;
            Ps[k][r] = Pb[(size_t)(i0 + r) * SLEN + (k0 + k)];
            Vs[r][k] = Vb[(k0 + r) * HD + k];
        }
        __syncthreads();
        #pragma unroll
        for (int k = 0; k < 64; k++) {
            float4 av = *(const float4*)&Ps[k][ty * 4];
            ulonglong2 bv = *(const ulonglong2*)&Vs[k][tx * 4];
            unsigned long long a;
            a = pack2(av.x, av.x);
            acc[0][0] = fma2(a, bv.x, acc[0][0]); acc[0][1] = fma2(a, bv.y, acc[0][1]);
            a = pack2(av.y, av.y);
            acc[1][0] = fma2(a, bv.x, acc[1][0]); acc[1][1] = fma2(a, bv.y, acc[1][1]);
            a = pack2(av.z, av.z);
            acc[2][0] = fma2(a, bv.x, acc[2][0]); acc[2][1] = fma2(a, bv.y, acc[2][1]);
            a = pack2(av.w, av.w);
            acc[3][0] = fma2(a, bv.x, acc[3][0]); acc[3][1] = fma2(a, bv.y, acc[3][1]);
        }
        __syncthreads();
    }

    int d0 = tx * 4;
    #pragma unroll
    for (int m = 0; m < 4; m++) {
        int row = bh * SLEN + i0 + ty * 4 + m;
        float s = g_invsum[row];
        float2 c01 = unpack2(acc[m][0]);
        float2 c23 = unpack2(acc[m][1]);
        *(float4*)&O[(size_t)row * HD + d0] =
            make_float4(c01.x * s, c01.y * s, c23.x * s, c23.y * s);
    }
}

// ---------------- launcher --------------------------------------------------
extern "C" void kernel_launch(void* const* d_in, const int* in_sizes, int n_in,
                              void* d_out, int out_size) {
    const float* Q = (const float*)d_in[0];
    const float* K = (const float*)d_in[1];
    const float* V = (const float*)d_in[2];
    float* O = (float*)d_out;

    zero_hist_kernel<<<NBINS / 4 / 256, 256>>>();
    norms_kernel<<<8192, 256>>>(Q, K);

    dim3 blk(16, 16);
    score_kernel<<<dim3(16, 16, NBH), blk>>>(Q, K);

    void* tmp;
    void* hist;
    cudaGetSymbolAddress(&tmp, g_temp);
    cudaGetSymbolAddress(&hist, g_hist);
    size_t temp_bytes = sizeof(g_temp);
    cub::DeviceScan::ExclusiveSum(tmp, temp_bytes,
                                  (unsigned int*)hist, (unsigned int*)hist,
                                  NBINS);

    rank_kernel<<<NROWS, 1024>>>();
    out_kernel<<<dim3(1, 16, NBH), blk>>>(V, O);
}

// round 4
// speedup vs baseline: 3.4338x; 1.0700x over previous
#include <cuda_runtime.h>
#include <cub/cub.cuh>
#include <cstdint>
#include <math.h>

// Problem shape (fixed): B=4, H=8, S=1024, D=64
#define SLEN 1024
#define HD   64
#define NBH  32
#define NROWS (NBH * SLEN)           // 32768
#define NTOT  ((size_t)NROWS * SLEN) // 33554432 = 2^25
#define BIN_SHIFT 9
#define NBINS (1u << 22)             // 4.19M bins, 16 MiB

typedef unsigned long long ull;

// ---------------- scratch ---------------------------------------------------
__device__ float g_score[NROWS * SLEN];          // 128 MiB raw scores
__device__ unsigned int g_hist[NBINS];           // 16 MiB
__device__ float g_invq[NROWS];
__device__ float g_invk[NROWS];
__device__ unsigned char g_temp[16u * 1024u * 1024u];  // CUB scan temp

// ---------------- f32x2 helpers (sm_103a) -----------------------------------
__device__ __forceinline__ ull pack2(float a, float b) {
    ull r; asm("mov.b64 %0, {%1,%2};" : "=l"(r) : "f"(a), "f"(b)); return r;
}
__device__ __forceinline__ ull fma2(ull a, ull b, ull c) {
    ull d; asm("fma.rn.f32x2 %0, %1, %2, %3;" : "=l"(d) : "l"(a), "l"(b), "l"(c));
    return d;
}
__device__ __forceinline__ float2 unpack2(ull v) {
    float2 f; asm("mov.b64 {%0,%1}, %2;" : "=f"(f.x), "=f"(f.y) : "l"(v));
    return f;
}
__device__ __forceinline__ unsigned bin_of(float v) {
    unsigned b = __float_as_uint(fabsf(v)) >> BIN_SHIFT;   // monotone in |v|
    return min(b, NBINS - 1u);
}
__device__ __forceinline__ unsigned sw(unsigned a) {      // 128B-line swizzle
    return a ^ ((a >> 3) & 0x70u);
}

// ---------------- kernel 0: zero histogram ----------------------------------
__global__ __launch_bounds__(256) void zero_hist_kernel() {
    unsigned i = blockIdx.x * 256 + threadIdx.x;
    ((uint4*)g_hist)[i] = make_uint4(0u, 0u, 0u, 0u);
}

// ---------------- kernel 1: inverse row norms -------------------------------
__global__ __launch_bounds__(256) void norms_kernel(const float* __restrict__ Q,
                                                    const float* __restrict__ K) {
    int w = (blockIdx.x * 256 + threadIdx.x) >> 5;
    int lane = threadIdx.x & 31;
    const float* src; float* dst; int row;
    if (w < NROWS) { src = Q; dst = g_invq; row = w; }
    else           { src = K; dst = g_invk; row = w - NROWS; }
    const float* p = src + (size_t)row * HD;
    float a = p[lane], b = p[lane + 32];
    float s = a * a + b * b;
    #pragma unroll
    for (int o = 16; o; o >>= 1) s += __shfl_xor_sync(0xffffffffu, s, o);
    if (lane == 0) dst[row] = 1.0f / (sqrtf(s) + 1e-5f);
}

// ---------------- kernel 2: score GEMM (128x128 tile, 8x8/thread) + hist ----
__global__ __launch_bounds__(256) void score_kernel(const float* __restrict__ Q,
                                                    const float* __restrict__ K) {
    __shared__ float Qs[128 * 33];   // i-major, odd stride -> conflict-free A
    __shared__ float Ks[32 * 128];   // k-major, SW128-swizzled -> conflict-free B
    int bh = blockIdx.z;
    int i0 = blockIdx.y * 128, j0 = blockIdx.x * 128;
    const float* Qb = Q + (size_t)bh * SLEN * HD;
    const float* Kb = K + (size_t)bh * SLEN * HD;
    int tid = threadIdx.x;
    int tx = tid & 15, ty = tid >> 4;   // tx: j-group (8 cols), ty: i-group (8 rows)

    ull acc[8][4];
    #pragma unroll
    for (int ii = 0; ii < 8; ii++)
        #pragma unroll
        for (int p = 0; p < 4; p++) acc[ii][p] = 0ull;

    #pragma unroll
    for (int c = 0; c < 2; c++) {          // k chunks of 32
        int k0 = c * 32;
        if (c) __syncthreads();
        #pragma unroll
        for (int pass = 0; pass < 4; pass++) {
            int row = (tid >> 3) + pass * 32;
            int kq = (tid & 7) * 4;
            float4 q4 = *(const float4*)&Qb[(i0 + row) * HD + k0 + kq];
            float* qd = &Qs[row * 33 + kq];
            qd[0] = q4.x; qd[1] = q4.y; qd[2] = q4.z; qd[3] = q4.w;
            float4 k4 = *(const float4*)&Kb[(j0 + row) * HD + k0 + kq];
            #pragma unroll
            for (int e = 0; e < 4; e++) {
                unsigned a = (unsigned)(kq + e) * 512u + (unsigned)row * 4u;
                Ks[sw(a) >> 2] = (&k4.x)[e];
            }
        }
        __syncthreads();
        #pragma unroll
        for (int k = 0; k < 32; k++) {
            unsigned a0 = (unsigned)k * 512u + (unsigned)tx * 32u;
            float4 b0 = *(const float4*)&Ks[sw(a0) >> 2];
            float4 b1 = *(const float4*)&Ks[sw(a0 + 16u) >> 2];
            ull bv0 = pack2(b0.x, b0.y), bv1 = pack2(b0.z, b0.w);
            ull bv2 = pack2(b1.x, b1.y), bv3 = pack2(b1.z, b1.w);
            #pragma unroll
            for (int ii = 0; ii < 8; ii++) {
                float av = Qs[(ty * 8 + ii) * 33 + k];
                ull a2 = pack2(av, av);
                acc[ii][0] = fma2(a2, bv0, acc[ii][0]);
                acc[ii][1] = fma2(a2, bv1, acc[ii][1]);
                acc[ii][2] = fma2(a2, bv2, acc[ii][2]);
                acc[ii][3] = fma2(a2, bv3, acc[ii][3]);
            }
        }
    }

    // epilogue: normalize, write raw scores, build histogram
    int jb = j0 + tx * 8;
    float ikv[8];
    #pragma unroll
    for (int jj = 0; jj < 8; jj++) ikv[jj] = g_invk[bh * SLEN + jb + jj];
    #pragma unroll
    for (int ii = 0; ii < 8; ii++) {
        int row = bh * SLEN + i0 + ty * 8 + ii;
        float iq = g_invq[row];
        float2 c0 = unpack2(acc[ii][0]);
        float2 c1 = unpack2(acc[ii][1]);
        float2 c2 = unpack2(acc[ii][2]);
        float2 c3 = unpack2(acc[ii][3]);
        float v[8];
        v[0] = c0.x * iq * ikv[0]; v[1] = c0.y * iq * ikv[1];
        v[2] = c1.x * iq * ikv[2]; v[3] = c1.y * iq * ikv[3];
        v[4] = c2.x * iq * ikv[4]; v[5] = c2.y * iq * ikv[5];
        v[6] = c3.x * iq * ikv[6]; v[7] = c3.y * iq * ikv[7];
        size_t idx = (size_t)row * SLEN + jb;
        *(float4*)&g_score[idx]     = make_float4(v[0], v[1], v[2], v[3]);
        *(float4*)&g_score[idx + 4] = make_float4(v[4], v[5], v[6], v[7]);
        #pragma unroll
        for (int e = 0; e < 8; e++) atomicAdd(&g_hist[bin_of(v[e])], 1u);
    }
}

// ---------------- kernel 3: fused rank-transform + rowsum + out GEMM --------
// 128 blocks, 256 rows each. Staging thread t owns row i0+t: reads raw P,
// assigns global rank via atomic, computes t=-log(rank-prob)*sign into smem,
// accumulates the row L1 sum in a register across all k chunks.
__global__ __launch_bounds__(256) void out_kernel(const float* __restrict__ V,
                                                  float* __restrict__ O) {
    __shared__ float Ts[256 * 33];   // t values, i-major odd stride
    __shared__ float Vs[32 * 64];    // k-major SW128-swizzled
    __shared__ float sinv[256];
    int blk = blockIdx.x;            // 0..127
    int bh = blk >> 2;
    int i0 = blk * 256;              // global row base
    const float* Vb = V + (size_t)bh * SLEN * HD;
    int tid = threadIdx.x;
    int tx = tid & 7, ty = tid >> 3; // tx: d-group (8), ty: i-group (8 rows)

    ull acc[8][4];
    #pragma unroll
    for (int ii = 0; ii < 8; ii++)
        #pragma unroll
        for (int p = 0; p < 4; p++) acc[ii][p] = 0ull;
    float srow = 0.0f;

    for (int c = 0; c < 32; c++) {   // k chunks of 32
        if (c) __syncthreads();
        // stage V chunk (swizzled)
        {
            int kv = tid >> 3;
            int d8 = (tid & 7) * 8;
            const float* vp = &Vb[(c * 32 + kv) * HD + d8];
            #pragma unroll
            for (int h = 0; h < 2; h++) {
                float4 v4 = *(const float4*)&vp[h * 4];
                unsigned a = (unsigned)kv * 256u + (unsigned)(d8 + h * 4) * 4u;
                *(float4*)&Vs[sw(a) >> 2] = v4;
            }
        }
        // stage + transform P: thread owns row i0+tid
        {
            const float* pr = g_score + (size_t)(i0 + tid) * SLEN + c * 32;
            float* trow = &Ts[tid * 33];
            #pragma unroll
            for (int q = 0; q < 8; q++) {
                float4 v4 = *(const float4*)&pr[q * 4];
                #pragma unroll
                for (int e = 0; e < 4; e++) {
                    float v = (&v4.x)[e];
                    unsigned p = atomicAdd(&g_hist[bin_of(v)], 1u);
                    float r = (float)p * 2.9802322e-8f + 2.9802322e-8f;
                    float t = -__logf(r);
                    t = (v > 0.0f) ? t : ((v < 0.0f) ? -t : 0.0f);
                    srow += fabsf(t);
                    trow[q * 4 + e] = t;
                }
            }
        }
        __syncthreads();
        #pragma unroll
        for (int k = 0; k < 32; k++) {
            unsigned a0 = (unsigned)k * 256u + (unsigned)tx * 32u;
            float4 b0 = *(const float4*)&Vs[sw(a0) >> 2];
            float4 b1 = *(const float4*)&Vs[sw(a0 + 16u) >> 2];
            ull bv0 = pack2(b0.x, b0.y), bv1 = pack2(b0.z, b0.w);
            ull bv2 = pack2(b1.x, b1.y), bv3 = pack2(b1.z, b1.w);
            #pragma unroll
            for (int ii = 0; ii < 8; ii++) {
                float av = Ts[(ty * 8 + ii) * 33 + k];
                ull a2 = pack2(av, av);
                acc[ii][0] = fma2(a2, bv0, acc[ii][0]);
                acc[ii][1] = fma2(a2, bv1, acc[ii][1]);
                acc[ii][2] = fma2(a2, bv2, acc[ii][2]);
                acc[ii][3] = fma2(a2, bv3, acc[ii][3]);
            }
        }
    }

    sinv[tid] = 1.0f / srow;
    __syncthreads();

    int d0 = tx * 8;
    #pragma unroll
    for (int ii = 0; ii < 8; ii++) {
        int lrow = ty * 8 + ii;
        float s = sinv[lrow];
        float2 c0 = unpack2(acc[ii][0]);
        float2 c1 = unpack2(acc[ii][1]);
        float2 c2 = unpack2(acc[ii][2]);
        float2 c3 = unpack2(acc[ii][3]);
        size_t oidx = (size_t)(i0 + lrow) * HD + d0;
        *(float4*)&O[oidx]     = make_float4(c0.x * s, c0.y * s, c1.x * s, c1.y * s);
        *(float4*)&O[oidx + 4] = make_float4(c2.x * s, c2.y * s, c3.x * s, c3.y * s);
    }
}

// ---------------- launcher ---------------------------------------------------
extern "C" void kernel_launch(void* const* d_in, const int* in_sizes, int n_in,
                              void* d_out, int out_size) {
    const float* Q = (const float*)d_in[0];
    const float* K = (const float*)d_in[1];
    const float* V = (const float*)d_in[2];
    float* O = (float*)d_out;

    zero_hist_kernel<<<NBINS / 4 / 256, 256>>>();
    norms_kernel<<<8192, 256>>>(Q, K);
    score_kernel<<<dim3(8, 8, NBH), 256>>>(Q, K);

    void* tmp; void* hist;
    cudaGetSymbolAddress(&tmp, g_temp);
    cudaGetSymbolAddress(&hist, g_hist);
    size_t temp_bytes = sizeof(g_temp);
    cub::DeviceScan::ExclusiveSum(tmp, temp_bytes,
                                  (unsigned int*)hist, (unsigned int*)hist,
                                  (int)NBINS);

    out_kernel<<<128, 256>>>(V, O);
}